// round 1
// baseline (speedup 1.0000x reference)
#include <cuda_runtime.h>

// Guided filter, RADIUS=8, EPS=0.01, input (8,3,1024,1024) fp32.
// 4-kernel separable pipeline:
//   K1: horizontal clipped box of {x, y, x*x, x*y}  -> g_s0..g_s3
//   K2: vertical sliding box + pointwise a,b        -> g_a, g_b
//   K3: horizontal clipped box of {a, b}            -> g_s0, g_s1 (reuse)
//   K4: vertical sliding box + out = A*x + B        -> d_out

#define W     1024
#define Hh    1024
#define IMGS  24
#define HW    (Hh * W)
#define TOTAL (IMGS * HW)
#define RAD   8
#define EPSF  0.01f

#define SEGR  128              // rows per thread in vertical kernels
#define SEGS  (Hh / SEGR)      // 8 segments per column

// Scratch: __device__ globals (allocation-free rule).
__device__ float g_s0[TOTAL];
__device__ float g_s1[TOTAL];
__device__ float g_s2[TOTAL];
__device__ float g_s3[TOTAL];
__device__ float g_a [TOTAL];
__device__ float g_b [TOTAL];

// ---------------------------------------------------------------------------
// K1: horizontal clipped box sums of x, y, x*x, x*y.
// Each thread produces 4 consecutive outputs from a 20-wide register window
// loaded with 5 float4 loads per input array (interior fast path).
// ---------------------------------------------------------------------------
__global__ void k_h1(const float* __restrict__ x, const float* __restrict__ y) {
    int t = blockIdx.x * blockDim.x + threadIdx.x;   // TOTAL/4 threads
    if (t >= TOTAL / 4) return;
    int lane    = t & 255;            // 256 quad-positions per row
    int col0    = lane << 2;          // first output column
    int rowbase = (t >> 8) << 10;     // (img*H + row) * W

    const float* xr = x + rowbase;
    const float* yr = y + rowbase;

    float xv[20], yv[20];
    if (col0 >= RAD && col0 + 11 < W) {
        #pragma unroll
        for (int q = 0; q < 5; q++) {
            float4 vx = *(const float4*)(xr + col0 - RAD + 4 * q);
            float4 vy = *(const float4*)(yr + col0 - RAD + 4 * q);
            xv[4*q+0] = vx.x; xv[4*q+1] = vx.y; xv[4*q+2] = vx.z; xv[4*q+3] = vx.w;
            yv[4*q+0] = vy.x; yv[4*q+1] = vy.y; yv[4*q+2] = vy.z; yv[4*q+3] = vy.w;
        }
    } else {
        #pragma unroll
        for (int j = 0; j < 20; j++) {
            int c = col0 - RAD + j;
            bool ok = ((unsigned)c < (unsigned)W);
            xv[j] = ok ? xr[c] : 0.0f;
            yv[j] = ok ? yr[c] : 0.0f;
        }
    }

    float sx = 0.f, sy = 0.f, sxx = 0.f, sxy = 0.f;
    #pragma unroll
    for (int j = 0; j < 17; j++) {
        float a = xv[j], b = yv[j];
        sx += a; sy += b;
        sxx = fmaf(a, a, sxx);
        sxy = fmaf(a, b, sxy);
    }
    float4 o0, o1, o2, o3;
    o0.x = sx; o1.x = sy; o2.x = sxx; o3.x = sxy;
    #pragma unroll
    for (int k = 1; k < 4; k++) {
        float ao = xv[k - 1], bo = yv[k - 1];
        float an = xv[k + 16], bn = yv[k + 16];
        sx  += an - ao;
        sy  += bn - bo;
        sxx += an * an - ao * ao;
        sxy += an * bn - ao * bo;
        if (k == 1) { o0.y = sx; o1.y = sy; o2.y = sxx; o3.y = sxy; }
        if (k == 2) { o0.z = sx; o1.z = sy; o2.z = sxx; o3.z = sxy; }
        if (k == 3) { o0.w = sx; o1.w = sy; o2.w = sxx; o3.w = sxy; }
    }
    int o = rowbase + col0;
    *(float4*)(g_s0 + o) = o0;
    *(float4*)(g_s1 + o) = o1;
    *(float4*)(g_s2 + o) = o2;
    *(float4*)(g_s3 + o) = o3;
}

// ---------------------------------------------------------------------------
// K2: vertical clipped box (sliding window, running sums) + pointwise a,b.
// One thread per (image, column, row-segment). Coalesced across columns.
// ---------------------------------------------------------------------------
__global__ void k_v1() {
    int t = blockIdx.x * blockDim.x + threadIdx.x;
    if (t >= IMGS * W * SEGS) return;
    int col  = t & (W - 1);
    int rest = t >> 10;
    int seg  = rest & (SEGS - 1);
    int img  = rest >> 3;            // SEGS == 8
    int base = img * HW + col;
    int s    = seg * SEGR;
    int nx   = min(W - 1, col + RAD) - max(0, col - RAD) + 1;

    float s0 = 0.f, s1 = 0.f, s2 = 0.f, s3 = 0.f;
    int r0 = max(0, s - RAD), r1 = min(Hh - 1, s + RAD);
    for (int r = r0; r <= r1; r++) {
        int o = base + r * W;
        s0 += g_s0[o]; s1 += g_s1[o]; s2 += g_s2[o]; s3 += g_s3[o];
    }
    for (int i = s; i < s + SEGR; i++) {
        int ny = min(Hh - 1, i + RAD) - max(0, i - RAD) + 1;
        float invN = __frcp_rn((float)(nx * ny));
        float mx = s0 * invN, my = s1 * invN;
        float varx = fmaf(-mx, mx, s2 * invN);
        float cov  = fmaf(-mx, my, s3 * invN);
        float a = __fdividef(cov, varx + EPSF);
        float b = fmaf(-a, mx, my);
        int o = base + i * W;
        g_a[o] = a;
        g_b[o] = b;
        int lead = i + RAD + 1, trail = i - RAD;
        if (lead < Hh) {
            int ol = base + lead * W;
            s0 += g_s0[ol]; s1 += g_s1[ol]; s2 += g_s2[ol]; s3 += g_s3[ol];
        }
        if (trail >= 0) {
            int ot = base + trail * W;
            s0 -= g_s0[ot]; s1 -= g_s1[ot]; s2 -= g_s2[ot]; s3 -= g_s3[ot];
        }
    }
}

// ---------------------------------------------------------------------------
// K3: horizontal clipped box sums of a, b  -> g_s0, g_s1 (buffers reused).
// ---------------------------------------------------------------------------
__global__ void k_h2() {
    int t = blockIdx.x * blockDim.x + threadIdx.x;
    if (t >= TOTAL / 4) return;
    int lane    = t & 255;
    int col0    = lane << 2;
    int rowbase = (t >> 8) << 10;

    const float* ar = g_a + rowbase;
    const float* br = g_b + rowbase;

    float av[20], bv[20];
    if (col0 >= RAD && col0 + 11 < W) {
        #pragma unroll
        for (int q = 0; q < 5; q++) {
            float4 va = *(const float4*)(ar + col0 - RAD + 4 * q);
            float4 vb = *(const float4*)(br + col0 - RAD + 4 * q);
            av[4*q+0] = va.x; av[4*q+1] = va.y; av[4*q+2] = va.z; av[4*q+3] = va.w;
            bv[4*q+0] = vb.x; bv[4*q+1] = vb.y; bv[4*q+2] = vb.z; bv[4*q+3] = vb.w;
        }
    } else {
        #pragma unroll
        for (int j = 0; j < 20; j++) {
            int c = col0 - RAD + j;
            bool ok = ((unsigned)c < (unsigned)W);
            av[j] = ok ? ar[c] : 0.0f;
            bv[j] = ok ? br[c] : 0.0f;
        }
    }

    float sa = 0.f, sb = 0.f;
    #pragma unroll
    for (int j = 0; j < 17; j++) { sa += av[j]; sb += bv[j]; }
    float4 oa, ob;
    oa.x = sa; ob.x = sb;
    sa += av[17] - av[0];  sb += bv[17] - bv[0];  oa.y = sa; ob.y = sb;
    sa += av[18] - av[1];  sb += bv[18] - bv[1];  oa.z = sa; ob.z = sb;
    sa += av[19] - av[2];  sb += bv[19] - bv[2];  oa.w = sa; ob.w = sb;

    int o = rowbase + col0;
    *(float4*)(g_s0 + o) = oa;
    *(float4*)(g_s1 + o) = ob;
}

// ---------------------------------------------------------------------------
// K4: vertical clipped box of ha, hb + final out = A*x + B.
// ---------------------------------------------------------------------------
__global__ void k_v2(const float* __restrict__ x, float* __restrict__ out) {
    int t = blockIdx.x * blockDim.x + threadIdx.x;
    if (t >= IMGS * W * SEGS) return;
    int col  = t & (W - 1);
    int rest = t >> 10;
    int seg  = rest & (SEGS - 1);
    int img  = rest >> 3;
    int base = img * HW + col;
    int s    = seg * SEGR;
    int nx   = min(W - 1, col + RAD) - max(0, col - RAD) + 1;

    float sa = 0.f, sb = 0.f;
    int r0 = max(0, s - RAD), r1 = min(Hh - 1, s + RAD);
    for (int r = r0; r <= r1; r++) {
        int o = base + r * W;
        sa += g_s0[o]; sb += g_s1[o];
    }
    for (int i = s; i < s + SEGR; i++) {
        int ny = min(Hh - 1, i + RAD) - max(0, i - RAD) + 1;
        float invN = __frcp_rn((float)(nx * ny));
        int o = base + i * W;
        out[o] = fmaf(sa * invN, x[o], sb * invN);
        int lead = i + RAD + 1, trail = i - RAD;
        if (lead < Hh) {
            int ol = base + lead * W;
            sa += g_s0[ol]; sb += g_s1[ol];
        }
        if (trail >= 0) {
            int ot = base + trail * W;
            sa -= g_s0[ot]; sb -= g_s1[ot];
        }
    }
}

extern "C" void kernel_launch(void* const* d_in, const int* in_sizes, int n_in,
                              void* d_out, int out_size) {
    const float* x = (const float*)d_in[0];
    const float* y = (const float*)d_in[1];
    float* out = (float*)d_out;

    int hblocks = (TOTAL / 4 + 255) / 256;          // 24576
    int vblocks = (IMGS * W * SEGS + 255) / 256;    // 768

    k_h1<<<hblocks, 256>>>(x, y);
    k_v1<<<vblocks, 256>>>();
    k_h2<<<hblocks, 256>>>();
    k_v2<<<vblocks, 256>>>(x, out);
}

// round 2
// speedup vs baseline: 1.6362x; 1.6362x over previous
#include <cuda_runtime.h>

// Guided filter, RADIUS=8, EPS=0.01, (8,3,1024,1024) fp32.
// Two fused kernels (each does horizontal box + vertical sliding box):
//   kA: x,y -> a,b        (vertical running sums of h-box(x,y,xx,xy); trail rows recomputed from L2)
//   kB: a,b,x -> out
// No shared memory; only 2 scratch arrays (a,b).

#define W     1024
#define Hh    1024
#define IMGS  24
#define HW    (Hh * W)
#define TOTAL (IMGS * HW)
#define RAD   8
#define EPSF  0.01f
#define SEGR  64
#define SEGS  (Hh / SEGR)

__device__ __align__(16) float g_a[TOTAL];
__device__ __align__(16) float g_b[TOTAL];

// Horizontal clipped-box window sums for 4 consecutive output cols (col0..col0+3)
// of one row, for x,y plus products. interior = full 20-wide window in range.
__device__ __forceinline__ void hsumA(const float* __restrict__ xr,
                                      const float* __restrict__ yr,
                                      int col0, bool interior,
                                      float hx[4], float hy[4],
                                      float hxx[4], float hxy[4]) {
    float xv[20], yv[20];
    if (interior) {
        #pragma unroll
        for (int q = 0; q < 5; q++) {
            float4 vx = *(const float4*)(xr + col0 - RAD + 4 * q);
            float4 vy = *(const float4*)(yr + col0 - RAD + 4 * q);
            xv[4*q+0]=vx.x; xv[4*q+1]=vx.y; xv[4*q+2]=vx.z; xv[4*q+3]=vx.w;
            yv[4*q+0]=vy.x; yv[4*q+1]=vy.y; yv[4*q+2]=vy.z; yv[4*q+3]=vy.w;
        }
    } else {
        #pragma unroll
        for (int j = 0; j < 20; j++) {
            int c = col0 - RAD + j;
            bool ok = ((unsigned)c < (unsigned)W);
            xv[j] = ok ? xr[c] : 0.0f;
            yv[j] = ok ? yr[c] : 0.0f;
        }
    }
    float sx = 0.f, sy = 0.f, sxx = 0.f, sxy = 0.f;
    #pragma unroll
    for (int j = 0; j < 17; j++) {
        float a = xv[j], b = yv[j];
        sx += a; sy += b;
        sxx = fmaf(a, a, sxx);
        sxy = fmaf(a, b, sxy);
    }
    hx[0] = sx; hy[0] = sy; hxx[0] = sxx; hxy[0] = sxy;
    #pragma unroll
    for (int k = 1; k < 4; k++) {
        float ao = xv[k-1], bo = yv[k-1];
        float an = xv[k+16], bn = yv[k+16];
        sx  += an - ao;
        sy  += bn - bo;
        sxx += an*an - ao*ao;
        sxy += an*bn - ao*bo;
        hx[k] = sx; hy[k] = sy; hxx[k] = sxx; hxy[k] = sxy;
    }
}

// Same for two plain arrays (no products).
__device__ __forceinline__ void hsumB(const float* __restrict__ ar,
                                      const float* __restrict__ br,
                                      int col0, bool interior,
                                      float ha[4], float hb[4]) {
    float av[20], bv[20];
    if (interior) {
        #pragma unroll
        for (int q = 0; q < 5; q++) {
            float4 va = *(const float4*)(ar + col0 - RAD + 4 * q);
            float4 vb = *(const float4*)(br + col0 - RAD + 4 * q);
            av[4*q+0]=va.x; av[4*q+1]=va.y; av[4*q+2]=va.z; av[4*q+3]=va.w;
            bv[4*q+0]=vb.x; bv[4*q+1]=vb.y; bv[4*q+2]=vb.z; bv[4*q+3]=vb.w;
        }
    } else {
        #pragma unroll
        for (int j = 0; j < 20; j++) {
            int c = col0 - RAD + j;
            bool ok = ((unsigned)c < (unsigned)W);
            av[j] = ok ? ar[c] : 0.0f;
            bv[j] = ok ? br[c] : 0.0f;
        }
    }
    float sa = 0.f, sb = 0.f;
    #pragma unroll
    for (int j = 0; j < 17; j++) { sa += av[j]; sb += bv[j]; }
    ha[0] = sa; hb[0] = sb;
    #pragma unroll
    for (int k = 1; k < 4; k++) {
        sa += av[k+16] - av[k-1];
        sb += bv[k+16] - bv[k-1];
        ha[k] = sa; hb[k] = sb;
    }
}

// ---------------------------------------------------------------------------
// Stage A: x,y -> a,b. One thread = 4 columns, marches SEGR rows.
// ---------------------------------------------------------------------------
__global__ void __launch_bounds__(256) kA(const float* __restrict__ x,
                                          const float* __restrict__ y) {
    int img  = blockIdx.y;
    int s    = blockIdx.x * SEGR;
    int col0 = threadIdx.x << 2;
    const float* xb = x + img * HW;
    const float* yb = y + img * HW;
    bool interior = (col0 >= RAD) && (col0 + 11 < W);

    float s0[4] = {0,0,0,0}, s1[4] = {0,0,0,0};
    float s2[4] = {0,0,0,0}, s3[4] = {0,0,0,0};
    float h0[4], h1[4], h2[4], h3[4];

    // warm-up: rows [max(0,s-8), s+8]
    for (int r = max(0, s - RAD); r <= s + RAD; r++) {
        hsumA(xb + r * W, yb + r * W, col0, interior, h0, h1, h2, h3);
        #pragma unroll
        for (int j = 0; j < 4; j++) {
            s0[j] += h0[j]; s1[j] += h1[j];
            s2[j] += h2[j]; s3[j] += h3[j];
        }
    }

    float nxv[4];
    #pragma unroll
    for (int j = 0; j < 4; j++) {
        int c = col0 + j;
        nxv[j] = (float)(min(W - 1, c + RAD) - max(0, c - RAD) + 1);
    }

    float* ga = g_a + img * HW;
    float* gb = g_b + img * HW;

    for (int o = s; o < s + SEGR; o++) {
        float ny = (float)(min(Hh - 1, o + RAD) - max(0, o - RAD) + 1);
        float4 av, bv;
        float ra[4], rb[4];
        #pragma unroll
        for (int j = 0; j < 4; j++) {
            float invN = __frcp_rn(nxv[j] * ny);
            float mx = s0[j] * invN, my = s1[j] * invN;
            float varx = fmaf(-mx, mx, s2[j] * invN);
            float cov  = fmaf(-mx, my, s3[j] * invN);
            float a = __fdividef(cov, varx + EPSF);
            ra[j] = a;
            rb[j] = fmaf(-a, mx, my);
        }
        av.x = ra[0]; av.y = ra[1]; av.z = ra[2]; av.w = ra[3];
        bv.x = rb[0]; bv.y = rb[1]; bv.z = rb[2]; bv.w = rb[3];
        *(float4*)(ga + o * W + col0) = av;
        *(float4*)(gb + o * W + col0) = bv;

        int lead = o + RAD + 1, trail = o - RAD;
        if (lead < Hh) {
            hsumA(xb + lead * W, yb + lead * W, col0, interior, h0, h1, h2, h3);
            #pragma unroll
            for (int j = 0; j < 4; j++) {
                s0[j] += h0[j]; s1[j] += h1[j];
                s2[j] += h2[j]; s3[j] += h3[j];
            }
        }
        if (trail >= 0) {
            hsumA(xb + trail * W, yb + trail * W, col0, interior, h0, h1, h2, h3);
            #pragma unroll
            for (int j = 0; j < 4; j++) {
                s0[j] -= h0[j]; s1[j] -= h1[j];
                s2[j] -= h2[j]; s3[j] -= h3[j];
            }
        }
    }
}

// ---------------------------------------------------------------------------
// Stage B: a,b,x -> out.
// ---------------------------------------------------------------------------
__global__ void __launch_bounds__(256) kB(const float* __restrict__ x,
                                          float* __restrict__ out) {
    int img  = blockIdx.y;
    int s    = blockIdx.x * SEGR;
    int col0 = threadIdx.x << 2;
    const float* ab = g_a + img * HW;
    const float* bb = g_b + img * HW;
    const float* xb = x + img * HW;
    float* ob = out + img * HW;
    bool interior = (col0 >= RAD) && (col0 + 11 < W);

    float sa[4] = {0,0,0,0}, sb[4] = {0,0,0,0};
    float ha[4], hb[4];

    for (int r = max(0, s - RAD); r <= s + RAD; r++) {
        hsumB(ab + r * W, bb + r * W, col0, interior, ha, hb);
        #pragma unroll
        for (int j = 0; j < 4; j++) { sa[j] += ha[j]; sb[j] += hb[j]; }
    }

    float nxv[4];
    #pragma unroll
    for (int j = 0; j < 4; j++) {
        int c = col0 + j;
        nxv[j] = (float)(min(W - 1, c + RAD) - max(0, c - RAD) + 1);
    }

    for (int o = s; o < s + SEGR; o++) {
        float ny = (float)(min(Hh - 1, o + RAD) - max(0, o - RAD) + 1);
        float4 xv = *(const float4*)(xb + o * W + col0);
        float4 ov;
        float xs[4] = {xv.x, xv.y, xv.z, xv.w};
        float os[4];
        #pragma unroll
        for (int j = 0; j < 4; j++) {
            float invN = __frcp_rn(nxv[j] * ny);
            os[j] = fmaf(sa[j] * invN, xs[j], sb[j] * invN);
        }
        ov.x = os[0]; ov.y = os[1]; ov.z = os[2]; ov.w = os[3];
        *(float4*)(ob + o * W + col0) = ov;

        int lead = o + RAD + 1, trail = o - RAD;
        if (lead < Hh) {
            hsumB(ab + lead * W, bb + lead * W, col0, interior, ha, hb);
            #pragma unroll
            for (int j = 0; j < 4; j++) { sa[j] += ha[j]; sb[j] += hb[j]; }
        }
        if (trail >= 0) {
            hsumB(ab + trail * W, bb + trail * W, col0, interior, ha, hb);
            #pragma unroll
            for (int j = 0; j < 4; j++) { sa[j] -= ha[j]; sb[j] -= hb[j]; }
        }
    }
}

extern "C" void kernel_launch(void* const* d_in, const int* in_sizes, int n_in,
                              void* d_out, int out_size) {
    const float* x = (const float*)d_in[0];
    const float* y = (const float*)d_in[1];
    float* out = (float*)d_out;

    dim3 grid(SEGS, IMGS);
    kA<<<grid, 256>>>(x, y);
    kB<<<grid, 256>>>(x, out);
}